// round 6
// baseline (speedup 1.0000x reference)
#include <cuda_runtime.h>

#define Z0f 10.0f
#define EPSf 1e-6f
#define AP_R2 400.0f   // (DIAMETER*0.5)^2

// 2 rays per thread, float2-granular I/O: no smem, no barriers, ~30 regs.
// P: [N,3] f32, V: [N,3] f32, out: [N,6] f32.
__global__ __launch_bounds__(256)
void refract_pair_kernel(const float2* __restrict__ P2,
                         const float2* __restrict__ V2,
                         const float* __restrict__ Rp,
                         const float* __restrict__ n1p,
                         const float* __restrict__ n2p,
                         float2* __restrict__ out2,
                         int nPairs)
{
    int i = blockIdx.x * blockDim.x + threadIdx.x;
    if (i >= nPairs) return;

    // Front-batched independent loads: 6 LDG.64 (streaming)
    float2 a0 = __ldcs(&P2[3*i + 0]);
    float2 a1 = __ldcs(&P2[3*i + 1]);
    float2 a2 = __ldcs(&P2[3*i + 2]);
    float2 b0 = __ldcs(&V2[3*i + 0]);
    float2 b1 = __ldcs(&V2[3*i + 1]);
    float2 b2 = __ldcs(&V2[3*i + 2]);

    const float R0   = Rp[0];
    const float eta  = n1p[0] / n2p[0];
    const float Cx   = Z0f + R0;
    const float invR = 1.0f / R0;
    const float eta2 = eta * eta;

    float pf[6] = {a0.x, a0.y, a1.x, a1.y, a2.x, a2.y};
    float vf[6] = {b0.x, b0.y, b1.x, b1.y, b2.x, b2.y};
    float of[12];

    #pragma unroll
    for (int j = 0; j < 2; j++) {
        float px = pf[3*j+0], py = pf[3*j+1], pz = pf[3*j+2];
        float vx = vf[3*j+0], vy = vf[3*j+1], vz = vf[3*j+2];

        // sphere intersection: t^2 + b t + c = 0  (|V| = 1)
        float pcx = px - Cx, pcy = py, pcz = pz;
        float b = 2.0f * (vx*pcx + vy*pcy + vz*pcz);
        float c = pcx*pcx + pcy*pcy + pcz*pcz - R0*R0;
        float disc = b*b - 4.0f*c;
        float sd = sqrtf(fmaxf(disc, 0.0f));
        float t1 = (-b - sd) * 0.5f;
        float t2 = (-b + sd) * 0.5f;
        float t  = (t1 > EPSf) ? t1 : t2;
        bool hit = (disc >= 0.0f) && (t > EPSf);

        // collision point + aperture clip
        float qx = px + t*vx, qy = py + t*vy, qz = pz + t*vz;
        float r2 = qy*qy + qz*qz;
        hit = hit && (r2 <= AP_R2);

        // surface normal oriented against the ray
        float nx = (qx - Cx) * invR, ny = qy * invR, nz = qz * invR;
        float ndotv = nx*vx + ny*vy + nz*vz;
        if (ndotv > 0.0f) { nx = -nx; ny = -ny; nz = -nz; }

        // Snell refraction (vector form)
        float cosi  = -(nx*vx + ny*vy + nz*vz);
        float sin2t = eta2 * (1.0f - cosi*cosi);
        bool refract_ok = (sin2t <= 1.0f);
        float cost = sqrtf(fmaxf(1.0f - sin2t, 0.0f));
        float k = eta*cosi - cost;

        bool valid = hit && refract_ok;
        of[6*j+0] = valid ? qx : 0.0f;
        of[6*j+1] = valid ? qy : 0.0f;
        of[6*j+2] = valid ? qz : 0.0f;
        of[6*j+3] = valid ? (eta*vx + k*nx) : 0.0f;
        of[6*j+4] = valid ? (eta*vy + k*ny) : 0.0f;
        of[6*j+5] = valid ? (eta*vz + k*nz) : 0.0f;
    }

    #pragma unroll
    for (int w = 0; w < 6; w++) {
        __stcs(&out2[6*i + w], make_float2(of[2*w], of[2*w+1]));
    }
}

// Scalar tail for N % 2 != 0 (not hit for N = 8388608).
__global__ void refract_tail_kernel(const float* __restrict__ P,
                                    const float* __restrict__ V,
                                    const float* __restrict__ Rp,
                                    const float* __restrict__ n1p,
                                    const float* __restrict__ n2p,
                                    float* __restrict__ out,
                                    int start, int N)
{
    int n = start + blockIdx.x * blockDim.x + threadIdx.x;
    if (n >= N) return;

    const float R0   = Rp[0];
    const float eta  = n1p[0] / n2p[0];
    const float Cx   = Z0f + R0;
    const float invR = 1.0f / R0;

    float px = P[3*n+0], py = P[3*n+1], pz = P[3*n+2];
    float vx = V[3*n+0], vy = V[3*n+1], vz = V[3*n+2];

    float pcx = px - Cx, pcy = py, pcz = pz;
    float b = 2.0f * (vx*pcx + vy*pcy + vz*pcz);
    float c = pcx*pcx + pcy*pcy + pcz*pcz - R0*R0;
    float disc = b*b - 4.0f*c;
    float sd = sqrtf(fmaxf(disc, 0.0f));
    float t1 = (-b - sd) * 0.5f;
    float t2 = (-b + sd) * 0.5f;
    float t  = (t1 > EPSf) ? t1 : t2;
    bool hit = (disc >= 0.0f) && (t > EPSf);

    float qx = px + t*vx, qy = py + t*vy, qz = pz + t*vz;
    float r2 = qy*qy + qz*qz;
    hit = hit && (r2 <= AP_R2);

    float nx = (qx - Cx) * invR, ny = qy * invR, nz = qz * invR;
    float ndotv = nx*vx + ny*vy + nz*vz;
    if (ndotv > 0.0f) { nx = -nx; ny = -ny; nz = -nz; }

    float cosi  = -(nx*vx + ny*vy + nz*vz);
    float sin2t = eta*eta * (1.0f - cosi*cosi);
    bool refract_ok = (sin2t <= 1.0f);
    float cost = sqrtf(fmaxf(1.0f - sin2t, 0.0f));
    float k = eta*cosi - cost;

    bool valid = hit && refract_ok;
    out[6*n+0] = valid ? qx : 0.0f;
    out[6*n+1] = valid ? qy : 0.0f;
    out[6*n+2] = valid ? qz : 0.0f;
    out[6*n+3] = valid ? (eta*vx + k*nx) : 0.0f;
    out[6*n+4] = valid ? (eta*vy + k*ny) : 0.0f;
    out[6*n+5] = valid ? (eta*vz + k*nz) : 0.0f;
}

extern "C" void kernel_launch(void* const* d_in, const int* in_sizes, int n_in,
                              void* d_out, int out_size)
{
    const float* P  = (const float*)d_in[0];
    const float* V  = (const float*)d_in[1];
    const float* R  = (const float*)d_in[2];
    const float* n1 = (const float*)d_in[3];
    const float* n2 = (const float*)d_in[4];
    float* out = (float*)d_out;

    int N = in_sizes[0] / 3;       // rays
    int nPairs = N / 2;
    int tail_start = nPairs * 2;

    if (nPairs > 0) {
        int threads = 256;
        int blocks = (nPairs + threads - 1) / threads;
        refract_pair_kernel<<<blocks, threads>>>(
            (const float2*)P, (const float2*)V, R, n1, n2, (float2*)out, nPairs);
    }
    if (tail_start < N) {
        int rem = N - tail_start;
        refract_tail_kernel<<<(rem + 255) / 256, 256>>>(
            P, V, R, n1, n2, out, tail_start, N);
    }
}

// round 7
// speedup vs baseline: 1.2452x; 1.2452x over previous
#include <cuda_runtime.h>

#define Z0f 10.0f
#define EPSf 1e-6f
#define AP_R2 400.0f   // (DIAMETER*0.5)^2

#define THREADS 256
#define RAYS_PER_BLOCK 1024        // 4 rays per thread
#define IN_F4_PER_ARR 768          // 1024 rays * 3 floats / 4

// Stage P,V through smem (packed -> aligned), compute 4 rays/thread,
// store 6 float4 directly to global. One barrier, 6 L1 ops/ray.
__global__ __launch_bounds__(THREADS)
void refract_hybrid_kernel(const float4* __restrict__ P4,
                           const float4* __restrict__ V4,
                           const float* __restrict__ Rp,
                           const float* __restrict__ n1p,
                           const float* __restrict__ n2p,
                           float4* __restrict__ out4)
{
    __shared__ float4 sP[IN_F4_PER_ARR];
    __shared__ float4 sV[IN_F4_PER_ARR];

    const int tid = threadIdx.x;
    const long blk = blockIdx.x;

    // ---- stage-in: 768 float4 of P + 768 of V, 3+3 per thread, streaming ----
    {
        const long base = blk * IN_F4_PER_ARR;
        #pragma unroll
        for (int k = 0; k < 3; k++) {
            int i = tid + k * THREADS;
            sP[i] = __ldcs(&P4[base + i]);
        }
        #pragma unroll
        for (int k = 0; k < 3; k++) {
            int i = tid + k * THREADS;
            sV[i] = __ldcs(&V4[base + i]);
        }
    }

    const float R0   = Rp[0];
    const float eta  = n1p[0] / n2p[0];
    const float Cx   = Z0f + R0;
    const float invR = 1.0f / R0;
    const float eta2 = eta * eta;

    __syncthreads();

    // ---- compute 4 rays: aligned 128-bit smem reads ----
    float4 p0 = sP[3*tid + 0];
    float4 p1 = sP[3*tid + 1];
    float4 p2 = sP[3*tid + 2];
    float4 v0 = sV[3*tid + 0];
    float4 v1 = sV[3*tid + 1];
    float4 v2 = sV[3*tid + 2];

    float pf[12] = {p0.x,p0.y,p0.z,p0.w, p1.x,p1.y,p1.z,p1.w, p2.x,p2.y,p2.z,p2.w};
    float vf[12] = {v0.x,v0.y,v0.z,v0.w, v1.x,v1.y,v1.z,v1.w, v2.x,v2.y,v2.z,v2.w};
    float of[24];

    #pragma unroll
    for (int j = 0; j < 4; j++) {
        float px = pf[3*j+0], py = pf[3*j+1], pz = pf[3*j+2];
        float vx = vf[3*j+0], vy = vf[3*j+1], vz = vf[3*j+2];

        // sphere intersection: t^2 + b t + c = 0  (|V| = 1)
        float pcx = px - Cx, pcy = py, pcz = pz;
        float b = 2.0f * (vx*pcx + vy*pcy + vz*pcz);
        float c = pcx*pcx + pcy*pcy + pcz*pcz - R0*R0;
        float disc = b*b - 4.0f*c;
        float sd = sqrtf(fmaxf(disc, 0.0f));
        float t1 = (-b - sd) * 0.5f;
        float t2 = (-b + sd) * 0.5f;
        float t  = (t1 > EPSf) ? t1 : t2;
        bool hit = (disc >= 0.0f) && (t > EPSf);

        // collision point + aperture clip
        float qx = px + t*vx, qy = py + t*vy, qz = pz + t*vz;
        float r2 = qy*qy + qz*qz;
        hit = hit && (r2 <= AP_R2);

        // surface normal oriented against the ray
        float nx = (qx - Cx) * invR, ny = qy * invR, nz = qz * invR;
        float ndotv = nx*vx + ny*vy + nz*vz;
        if (ndotv > 0.0f) { nx = -nx; ny = -ny; nz = -nz; }

        // Snell refraction (vector form)
        float cosi  = -(nx*vx + ny*vy + nz*vz);
        float sin2t = eta2 * (1.0f - cosi*cosi);
        bool refract_ok = (sin2t <= 1.0f);
        float cost = sqrtf(fmaxf(1.0f - sin2t, 0.0f));
        float k = eta*cosi - cost;

        bool valid = hit && refract_ok;
        of[6*j+0] = valid ? qx : 0.0f;
        of[6*j+1] = valid ? qy : 0.0f;
        of[6*j+2] = valid ? qz : 0.0f;
        of[6*j+3] = valid ? (eta*vx + k*nx) : 0.0f;
        of[6*j+4] = valid ? (eta*vy + k*ny) : 0.0f;
        of[6*j+5] = valid ? (eta*vz + k*nz) : 0.0f;
    }

    // ---- direct vectorized store: rays 4t..4t+3 -> float4 6t..6t+5 ----
    {
        const long obase = blk * (RAYS_PER_BLOCK * 6 / 4);  // 1536 float4/block
        #pragma unroll
        for (int w = 0; w < 6; w++) {
            __stcs(&out4[obase + 6*tid + w],
                   make_float4(of[4*w+0], of[4*w+1], of[4*w+2], of[4*w+3]));
        }
    }
}

// Scalar tail for leftover rays (N % 1024 != 0). Not hit for N = 8388608.
__global__ void refract_tail_kernel(const float* __restrict__ P,
                                    const float* __restrict__ V,
                                    const float* __restrict__ Rp,
                                    const float* __restrict__ n1p,
                                    const float* __restrict__ n2p,
                                    float* __restrict__ out,
                                    int start, int N)
{
    int n = start + blockIdx.x * blockDim.x + threadIdx.x;
    if (n >= N) return;

    const float R0   = Rp[0];
    const float eta  = n1p[0] / n2p[0];
    const float Cx   = Z0f + R0;
    const float invR = 1.0f / R0;

    float px = P[3*n+0], py = P[3*n+1], pz = P[3*n+2];
    float vx = V[3*n+0], vy = V[3*n+1], vz = V[3*n+2];

    float pcx = px - Cx, pcy = py, pcz = pz;
    float b = 2.0f * (vx*pcx + vy*pcy + vz*pcz);
    float c = pcx*pcx + pcy*pcy + pcz*pcz - R0*R0;
    float disc = b*b - 4.0f*c;
    float sd = sqrtf(fmaxf(disc, 0.0f));
    float t1 = (-b - sd) * 0.5f;
    float t2 = (-b + sd) * 0.5f;
    float t  = (t1 > EPSf) ? t1 : t2;
    bool hit = (disc >= 0.0f) && (t > EPSf);

    float qx = px + t*vx, qy = py + t*vy, qz = pz + t*vz;
    float r2 = qy*qy + qz*qz;
    hit = hit && (r2 <= AP_R2);

    float nx = (qx - Cx) * invR, ny = qy * invR, nz = qz * invR;
    float ndotv = nx*vx + ny*vy + nz*vz;
    if (ndotv > 0.0f) { nx = -nx; ny = -ny; nz = -nz; }

    float cosi  = -(nx*vx + ny*vy + nz*vz);
    float sin2t = eta*eta * (1.0f - cosi*cosi);
    bool refract_ok = (sin2t <= 1.0f);
    float cost = sqrtf(fmaxf(1.0f - sin2t, 0.0f));
    float k = eta*cosi - cost;

    bool valid = hit && refract_ok;
    out[6*n+0] = valid ? qx : 0.0f;
    out[6*n+1] = valid ? qy : 0.0f;
    out[6*n+2] = valid ? qz : 0.0f;
    out[6*n+3] = valid ? (eta*vx + k*nx) : 0.0f;
    out[6*n+4] = valid ? (eta*vy + k*ny) : 0.0f;
    out[6*n+5] = valid ? (eta*vz + k*nz) : 0.0f;
}

extern "C" void kernel_launch(void* const* d_in, const int* in_sizes, int n_in,
                              void* d_out, int out_size)
{
    const float* P  = (const float*)d_in[0];
    const float* V  = (const float*)d_in[1];
    const float* R  = (const float*)d_in[2];
    const float* n1 = (const float*)d_in[3];
    const float* n2 = (const float*)d_in[4];
    float* out = (float*)d_out;

    int N = in_sizes[0] / 3;                 // rays
    int fullBlocks = N / RAYS_PER_BLOCK;
    int tail_start = fullBlocks * RAYS_PER_BLOCK;

    if (fullBlocks > 0) {
        refract_hybrid_kernel<<<fullBlocks, THREADS>>>(
            (const float4*)P, (const float4*)V, R, n1, n2, (float4*)out);
    }
    if (tail_start < N) {
        int rem = N - tail_start;
        refract_tail_kernel<<<(rem + 255) / 256, 256>>>(
            P, V, R, n1, n2, out, tail_start, N);
    }
}

// round 8
// speedup vs baseline: 1.3339x; 1.0712x over previous
#include <cuda_runtime.h>
#include <cstdint>

#define Z0f 10.0f
#define EPSf 1e-6f
#define AP_R2 400.0f   // (DIAMETER*0.5)^2

#define THREADS 256
#define TILE_RAYS 256
#define IN_F4 192          // float4 per input array per tile (256*3/4)
#define IN_F4_TOT 384      // P + V
#define OUT_F4 384         // 256*6/4

__device__ __forceinline__ uint32_t smem_u32(const void* p) {
    return (uint32_t)__cvta_generic_to_shared(p);
}
__device__ __forceinline__ void cp_async16(uint32_t dst, const void* src) {
    asm volatile("cp.async.cg.shared.global [%0], [%1], 16;" :: "r"(dst), "l"(src));
}
__device__ __forceinline__ void cp_commit() {
    asm volatile("cp.async.commit_group;");
}
template<int W> __device__ __forceinline__ void cp_wait() {
    asm volatile("cp.async.wait_group %0;" :: "n"(W));
}

// Issue async copies for one tile into buf: [0:192)=P float4, [192:384)=V float4.
__device__ __forceinline__ void prefetch_tile(float4* buf,
                                              const float4* __restrict__ P4,
                                              const float4* __restrict__ V4,
                                              long t, int tid)
{
    const float4* Pb = P4 + t * IN_F4;
    const float4* Vb = V4 + t * IN_F4;
    // i = tid in [0,256): first 192 from P, rest from V
    {
        const void* src = (tid < IN_F4) ? (const void*)(Pb + tid)
                                        : (const void*)(Vb + (tid - IN_F4));
        cp_async16(smem_u32(buf + tid), src);
    }
    // i2 = tid + 256 in [256,384): always V
    if (tid < IN_F4_TOT - THREADS) {
        int i2 = tid + THREADS;
        cp_async16(smem_u32(buf + i2), (const void*)(Vb + (i2 - IN_F4)));
    }
}

// Persistent double-buffered pipeline: 1 ray/thread compute, smem staging
// both directions, cp.async.cg overlapped stage-in (L1 bypass).
__global__ __launch_bounds__(THREADS)
void refract_pipe_kernel(const float4* __restrict__ P4,
                         const float4* __restrict__ V4,
                         const float* __restrict__ Rp,
                         const float* __restrict__ n1p,
                         const float* __restrict__ n2p,
                         float4* __restrict__ out4,
                         int nTiles)
{
    __shared__ float4 sIn[2][IN_F4_TOT];
    __shared__ float4 sOut[OUT_F4];

    const int tid = threadIdx.x;
    const int stride = gridDim.x;

    const float R0   = Rp[0];
    const float eta  = n1p[0] / n2p[0];
    const float Cx   = Z0f + R0;
    const float invR = 1.0f / R0;
    const float eta2 = eta * eta;

    long t = blockIdx.x;
    if (t >= nTiles) return;

    // prime the pipeline
    prefetch_tile(sIn[0], P4, V4, t, tid);
    cp_commit();

    int buf = 0;
    for (; t < nTiles; t += stride) {
        long tn = t + stride;
        bool has_next = (tn < nTiles);
        if (has_next) {
            prefetch_tile(sIn[buf ^ 1], P4, V4, tn, tid);
            cp_commit();
            cp_wait<1>();   // current tile's group has landed
        } else {
            cp_wait<0>();
        }
        __syncthreads();    // smem visible to all; also fences prior sOut reads

        // ---- compute: one ray per thread from smem ----
        {
            const float* f = reinterpret_cast<const float*>(sIn[buf]);
            float px = f[3*tid + 0], py = f[3*tid + 1], pz = f[3*tid + 2];
            float vx = f[768 + 3*tid + 0], vy = f[768 + 3*tid + 1], vz = f[768 + 3*tid + 2];

            // sphere intersection: t^2 + b t + c = 0  (|V| = 1)
            float pcx = px - Cx, pcy = py, pcz = pz;
            float b = 2.0f * (vx*pcx + vy*pcy + vz*pcz);
            float c = pcx*pcx + pcy*pcy + pcz*pcz - R0*R0;
            float disc = b*b - 4.0f*c;
            float sd = sqrtf(fmaxf(disc, 0.0f));
            float t1 = (-b - sd) * 0.5f;
            float t2 = (-b + sd) * 0.5f;
            float tt = (t1 > EPSf) ? t1 : t2;
            bool hit = (disc >= 0.0f) && (tt > EPSf);

            // collision point + aperture clip
            float qx = px + tt*vx, qy = py + tt*vy, qz = pz + tt*vz;
            float r2 = qy*qy + qz*qz;
            hit = hit && (r2 <= AP_R2);

            // surface normal oriented against the ray
            float nx = (qx - Cx) * invR, ny = qy * invR, nz = qz * invR;
            float ndotv = nx*vx + ny*vy + nz*vz;
            if (ndotv > 0.0f) { nx = -nx; ny = -ny; nz = -nz; }

            // Snell refraction (vector form)
            float cosi  = -(nx*vx + ny*vy + nz*vz);
            float sin2t = eta2 * (1.0f - cosi*cosi);
            bool refract_ok = (sin2t <= 1.0f);
            float cost = sqrtf(fmaxf(1.0f - sin2t, 0.0f));
            float k = eta*cosi - cost;

            bool valid = hit && refract_ok;
            float* so = reinterpret_cast<float*>(sOut);
            so[6*tid + 0] = valid ? qx : 0.0f;
            so[6*tid + 1] = valid ? qy : 0.0f;
            so[6*tid + 2] = valid ? qz : 0.0f;
            so[6*tid + 3] = valid ? (eta*vx + k*nx) : 0.0f;
            so[6*tid + 4] = valid ? (eta*vy + k*ny) : 0.0f;
            so[6*tid + 5] = valid ? (eta*vz + k*nz) : 0.0f;
        }

        __syncthreads();

        // ---- stage-out: 384 float4 streaming stores ----
        {
            const long obase = t * OUT_F4;
            __stcs(&out4[obase + tid], sOut[tid]);
            if (tid < OUT_F4 - THREADS) {
                int i2 = tid + THREADS;
                __stcs(&out4[obase + i2], sOut[i2]);
            }
        }

        buf ^= 1;
    }
}

// Scalar tail for leftover rays (N % 256 != 0). Not hit for N = 8388608.
__global__ void refract_tail_kernel(const float* __restrict__ P,
                                    const float* __restrict__ V,
                                    const float* __restrict__ Rp,
                                    const float* __restrict__ n1p,
                                    const float* __restrict__ n2p,
                                    float* __restrict__ out,
                                    int start, int N)
{
    int n = start + blockIdx.x * blockDim.x + threadIdx.x;
    if (n >= N) return;

    const float R0   = Rp[0];
    const float eta  = n1p[0] / n2p[0];
    const float Cx   = Z0f + R0;
    const float invR = 1.0f / R0;

    float px = P[3*n+0], py = P[3*n+1], pz = P[3*n+2];
    float vx = V[3*n+0], vy = V[3*n+1], vz = V[3*n+2];

    float pcx = px - Cx, pcy = py, pcz = pz;
    float b = 2.0f * (vx*pcx + vy*pcy + vz*pcz);
    float c = pcx*pcx + pcy*pcy + pcz*pcz - R0*R0;
    float disc = b*b - 4.0f*c;
    float sd = sqrtf(fmaxf(disc, 0.0f));
    float t1 = (-b - sd) * 0.5f;
    float t2 = (-b + sd) * 0.5f;
    float t  = (t1 > EPSf) ? t1 : t2;
    bool hit = (disc >= 0.0f) && (t > EPSf);

    float qx = px + t*vx, qy = py + t*vy, qz = pz + t*vz;
    float r2 = qy*qy + qz*qz;
    hit = hit && (r2 <= AP_R2);

    float nx = (qx - Cx) * invR, ny = qy * invR, nz = qz * invR;
    float ndotv = nx*vx + ny*vy + nz*vz;
    if (ndotv > 0.0f) { nx = -nx; ny = -ny; nz = -nz; }

    float cosi  = -(nx*vx + ny*vy + nz*vz);
    float sin2t = eta*eta * (1.0f - cosi*cosi);
    bool refract_ok = (sin2t <= 1.0f);
    float cost = sqrtf(fmaxf(1.0f - sin2t, 0.0f));
    float k = eta*cosi - cost;

    bool valid = hit && refract_ok;
    out[6*n+0] = valid ? qx : 0.0f;
    out[6*n+1] = valid ? qy : 0.0f;
    out[6*n+2] = valid ? qz : 0.0f;
    out[6*n+3] = valid ? (eta*vx + k*nx) : 0.0f;
    out[6*n+4] = valid ? (eta*vy + k*ny) : 0.0f;
    out[6*n+5] = valid ? (eta*vz + k*nz) : 0.0f;
}

extern "C" void kernel_launch(void* const* d_in, const int* in_sizes, int n_in,
                              void* d_out, int out_size)
{
    const float* P  = (const float*)d_in[0];
    const float* V  = (const float*)d_in[1];
    const float* R  = (const float*)d_in[2];
    const float* n1 = (const float*)d_in[3];
    const float* n2 = (const float*)d_in[4];
    float* out = (float*)d_out;

    int N = in_sizes[0] / 3;             // rays
    int nTiles = N / TILE_RAYS;
    int tail_start = nTiles * TILE_RAYS;

    if (nTiles > 0) {
        // 8 persistent blocks per SM (148 SMs on sm_100a)
        int grid = 148 * 8;
        if (grid > nTiles) grid = nTiles;
        refract_pipe_kernel<<<grid, THREADS>>>(
            (const float4*)P, (const float4*)V, R, n1, n2, (float4*)out, nTiles);
    }
    if (tail_start < N) {
        int rem = N - tail_start;
        refract_tail_kernel<<<(rem + 255) / 256, 256>>>(
            P, V, R, n1, n2, out, tail_start, N);
    }
}

// round 9
// speedup vs baseline: 1.5176x; 1.1377x over previous
#include <cuda_runtime.h>

#define Z0f 10.0f
#define EPSf 1e-6f
#define AP_R2 400.0f   // (DIAMETER*0.5)^2

__device__ __forceinline__ float4 shflx1_f4(float4 v) {
    float4 r;
    r.x = __shfl_xor_sync(0xffffffffu, v.x, 1);
    r.y = __shfl_xor_sync(0xffffffffu, v.y, 1);
    r.z = __shfl_xor_sync(0xffffffffu, v.z, 1);
    r.w = __shfl_xor_sync(0xffffffffu, v.w, 1);
    return r;
}

// One ray: inputs (px..vz), writes 6 floats into o[0..5].
__device__ __forceinline__ void trace_ray(float px, float py, float pz,
                                          float vx, float vy, float vz,
                                          float R0, float Cx, float invR,
                                          float eta, float eta2,
                                          float* o)
{
    // sphere intersection: t^2 + b t + c = 0  (|V| = 1)
    float pcx = px - Cx, pcy = py, pcz = pz;
    float b = 2.0f * (vx*pcx + vy*pcy + vz*pcz);
    float c = pcx*pcx + pcy*pcy + pcz*pcz - R0*R0;
    float disc = b*b - 4.0f*c;
    float sd = sqrtf(fmaxf(disc, 0.0f));
    float t1 = (-b - sd) * 0.5f;
    float t2 = (-b + sd) * 0.5f;
    float t  = (t1 > EPSf) ? t1 : t2;
    bool hit = (disc >= 0.0f) && (t > EPSf);

    // collision point + aperture clip
    float qx = px + t*vx, qy = py + t*vy, qz = pz + t*vz;
    float r2 = qy*qy + qz*qz;
    hit = hit && (r2 <= AP_R2);

    // surface normal oriented against the ray
    float nx = (qx - Cx) * invR, ny = qy * invR, nz = qz * invR;
    float ndotv = nx*vx + ny*vy + nz*vz;
    if (ndotv > 0.0f) { nx = -nx; ny = -ny; nz = -nz; }

    // Snell refraction (vector form)
    float cosi  = -(nx*vx + ny*vy + nz*vz);
    float sin2t = eta2 * (1.0f - cosi*cosi);
    bool refract_ok = (sin2t <= 1.0f);
    float cost = sqrtf(fmaxf(1.0f - sin2t, 0.0f));
    float k = eta*cosi - cost;

    bool valid = hit && refract_ok;
    o[0] = valid ? qx : 0.0f;
    o[1] = valid ? qy : 0.0f;
    o[2] = valid ? qz : 0.0f;
    o[3] = valid ? (eta*vx + k*nx) : 0.0f;
    o[4] = valid ? (eta*vy + k*ny) : 0.0f;
    o[5] = valid ? (eta*vz + k*nz) : 0.0f;
}

// 2 rays per thread; a thread-PAIR owns 4 rays = 3 float4 of P/V and
// 6 float4 of out. All global traffic is 128-bit; inputs distributed by
// two shfl.xor exchanges; outputs need no exchange. No smem, no barriers.
__global__ __launch_bounds__(256, 7)
void refract_shfl_kernel(const float4* __restrict__ P4,
                         const float4* __restrict__ V4,
                         const float* __restrict__ Rp,
                         const float* __restrict__ n1p,
                         const float* __restrict__ n2p,
                         float4* __restrict__ out4)
{
    const int t = blockIdx.x * blockDim.x + threadIdx.x;  // grid sized exactly
    const int p = t >> 1;      // pair index: rays 4p..4p+3
    const int s = t & 1;
    const long i3 = 3L * p;

    // Loads: even lane -> f0 (r0) and f2 (r1); odd lane -> f1 (r0).
    float4 r0p = __ldcs(&P4[i3 + s]);
    float4 r0v = __ldcs(&V4[i3 + s]);
    float4 r1p = make_float4(0.f, 0.f, 0.f, 0.f);
    float4 r1v = make_float4(0.f, 0.f, 0.f, 0.f);
    if (s == 0) {
        r1p = __ldcs(&P4[i3 + 2]);
        r1v = __ldcs(&V4[i3 + 2]);
    }

    // Exchange within pair:
    //   e0 = partner's r0  (even receives f1; odd receives f0, unused)
    //   e1 = partner's r1  (odd receives f2; even receives zeros, unused)
    float4 e0p = shflx1_f4(r0p);
    float4 e1p = shflx1_f4(r1p);
    float4 e0v = shflx1_f4(r0v);
    float4 e1v = shflx1_f4(r1v);

    const float R0   = Rp[0];
    const float eta  = n1p[0] / n2p[0];
    const float Cx   = Z0f + R0;
    const float invR = 1.0f / R0;
    const float eta2 = eta * eta;

    // Select this thread's two rays.
    // even: rayA = floats 0..2 of f0, rayB = f0.w, f1.x, f1.y
    // odd : rayA = f1.z, f1.w, f2.x,  rayB = f2.y, f2.z, f2.w
    float pax, pay, paz, pbx, pby, pbz;
    float vax, vay, vaz, vbx, vby, vbz;
    if (s == 0) {
        pax = r0p.x; pay = r0p.y; paz = r0p.z;
        pbx = r0p.w; pby = e0p.x; pbz = e0p.y;
        vax = r0v.x; vay = r0v.y; vaz = r0v.z;
        vbx = r0v.w; vby = e0v.x; vbz = e0v.y;
    } else {
        pax = r0p.z; pay = r0p.w; paz = e1p.x;
        pbx = e1p.y; pby = e1p.z; pbz = e1p.w;
        vax = r0v.z; vay = r0v.w; vaz = e1v.x;
        vbx = e1v.y; vby = e1v.z; vbz = e1v.w;
    }

    float of[12];
    trace_ray(pax, pay, paz, vax, vay, vaz, R0, Cx, invR, eta, eta2, of);
    trace_ray(pbx, pby, pbz, vbx, vby, vbz, R0, Cx, invR, eta, eta2, of + 6);

    // Store 3 aligned float4: even -> out4[6p+0..2], odd -> out4[6p+3..5]
    const long obase = 6L * p + 3 * s;
    __stcs(&out4[obase + 0], make_float4(of[0], of[1], of[2],  of[3]));
    __stcs(&out4[obase + 1], make_float4(of[4], of[5], of[6],  of[7]));
    __stcs(&out4[obase + 2], make_float4(of[8], of[9], of[10], of[11]));
}

// Scalar tail for leftover rays. Not hit for N = 8388608.
__global__ void refract_tail_kernel(const float* __restrict__ P,
                                    const float* __restrict__ V,
                                    const float* __restrict__ Rp,
                                    const float* __restrict__ n1p,
                                    const float* __restrict__ n2p,
                                    float* __restrict__ out,
                                    int start, int N)
{
    int n = start + blockIdx.x * blockDim.x + threadIdx.x;
    if (n >= N) return;

    const float R0   = Rp[0];
    const float eta  = n1p[0] / n2p[0];
    const float Cx   = Z0f + R0;
    const float invR = 1.0f / R0;

    float px = P[3*n+0], py = P[3*n+1], pz = P[3*n+2];
    float vx = V[3*n+0], vy = V[3*n+1], vz = V[3*n+2];

    float pcx = px - Cx, pcy = py, pcz = pz;
    float b = 2.0f * (vx*pcx + vy*pcy + vz*pcz);
    float c = pcx*pcx + pcy*pcy + pcz*pcz - R0*R0;
    float disc = b*b - 4.0f*c;
    float sd = sqrtf(fmaxf(disc, 0.0f));
    float t1 = (-b - sd) * 0.5f;
    float t2 = (-b + sd) * 0.5f;
    float t  = (t1 > EPSf) ? t1 : t2;
    bool hit = (disc >= 0.0f) && (t > EPSf);

    float qx = px + t*vx, qy = py + t*vy, qz = pz + t*vz;
    float r2 = qy*qy + qz*qz;
    hit = hit && (r2 <= AP_R2);

    float nx = (qx - Cx) * invR, ny = qy * invR, nz = qz * invR;
    float ndotv = nx*vx + ny*vy + nz*vz;
    if (ndotv > 0.0f) { nx = -nx; ny = -ny; nz = -nz; }

    float cosi  = -(nx*vx + ny*vy + nz*vz);
    float sin2t = eta*eta * (1.0f - cosi*cosi);
    bool refract_ok = (sin2t <= 1.0f);
    float cost = sqrtf(fmaxf(1.0f - sin2t, 0.0f));
    float k = eta*cosi - cost;

    bool valid = hit && refract_ok;
    out[6*n+0] = valid ? qx : 0.0f;
    out[6*n+1] = valid ? qy : 0.0f;
    out[6*n+2] = valid ? qz : 0.0f;
    out[6*n+3] = valid ? (eta*vx + k*nx) : 0.0f;
    out[6*n+4] = valid ? (eta*vy + k*ny) : 0.0f;
    out[6*n+5] = valid ? (eta*vz + k*nz) : 0.0f;
}

extern "C" void kernel_launch(void* const* d_in, const int* in_sizes, int n_in,
                              void* d_out, int out_size)
{
    const float* P  = (const float*)d_in[0];
    const float* V  = (const float*)d_in[1];
    const float* R  = (const float*)d_in[2];
    const float* n1 = (const float*)d_in[3];
    const float* n2 = (const float*)d_in[4];
    float* out = (float*)d_out;

    int N = in_sizes[0] / 3;            // rays
    // Main kernel covers rays in chunks of 512 (256 threads * 2 rays, full
    // blocks only so every warp is complete for shfl).
    long nGroups = N / 4;               // thread pairs
    long threadsWanted = nGroups * 2;
    long fullBlocks = threadsWanted / 256;
    long rays_main = fullBlocks * 256 * 2;

    if (fullBlocks > 0) {
        refract_shfl_kernel<<<(unsigned)fullBlocks, 256>>>(
            (const float4*)P, (const float4*)V, R, n1, n2, (float4*)out);
    }
    if (rays_main < N) {
        int rem = (int)(N - rays_main);
        refract_tail_kernel<<<(rem + 255) / 256, 256>>>(
            P, V, R, n1, n2, out, (int)rays_main, N);
    }
}

// round 10
// speedup vs baseline: 1.5228x; 1.0034x over previous
#include <cuda_runtime.h>

#define Z0f 10.0f
#define EPSf 1e-6f
#define AP_R2 400.0f   // (DIAMETER*0.5)^2

// One ray: inputs (px..vz), writes 6 floats into o[0..5].
__device__ __forceinline__ void trace_ray(float px, float py, float pz,
                                          float vx, float vy, float vz,
                                          float R0, float Cx, float invR,
                                          float eta, float eta2,
                                          float* o)
{
    // sphere intersection: t^2 + b t + c = 0  (|V| = 1)
    float pcx = px - Cx, pcy = py, pcz = pz;
    float b = 2.0f * (vx*pcx + vy*pcy + vz*pcz);
    float c = pcx*pcx + pcy*pcy + pcz*pcz - R0*R0;
    float disc = b*b - 4.0f*c;
    float sd = sqrtf(fmaxf(disc, 0.0f));
    float t1 = (-b - sd) * 0.5f;
    float t2 = (-b + sd) * 0.5f;
    float t  = (t1 > EPSf) ? t1 : t2;
    bool hit = (disc >= 0.0f) && (t > EPSf);

    // collision point + aperture clip
    float qx = px + t*vx, qy = py + t*vy, qz = pz + t*vz;
    float r2 = qy*qy + qz*qz;
    hit = hit && (r2 <= AP_R2);

    // surface normal oriented against the ray
    float nx = (qx - Cx) * invR, ny = qy * invR, nz = qz * invR;
    float ndotv = nx*vx + ny*vy + nz*vz;
    if (ndotv > 0.0f) { nx = -nx; ny = -ny; nz = -nz; }

    // Snell refraction (vector form)
    float cosi  = -(nx*vx + ny*vy + nz*vz);
    float sin2t = eta2 * (1.0f - cosi*cosi);
    bool refract_ok = (sin2t <= 1.0f);
    float cost = sqrtf(fmaxf(1.0f - sin2t, 0.0f));
    float k = eta*cosi - cost;

    bool valid = hit && refract_ok;
    o[0] = valid ? qx : 0.0f;
    o[1] = valid ? qy : 0.0f;
    o[2] = valid ? qz : 0.0f;
    o[3] = valid ? (eta*vx + k*nx) : 0.0f;
    o[4] = valid ? (eta*vy + k*ny) : 0.0f;
    o[5] = valid ? (eta*vz + k*nz) : 0.0f;
}

// 2 rays/thread; a thread-pair owns 4 rays = 3 float4 of P/V, 6 float4 out.
// Even lane loads f0,f1; odd loads f2. Only f1.zw crosses lanes:
// 4 shfl.b32 per thread total. All global traffic 128-bit, no smem/barriers.
__global__ __launch_bounds__(256, 7)
void refract_shfl2_kernel(const float4* __restrict__ P4,
                          const float4* __restrict__ V4,
                          const float* __restrict__ Rp,
                          const float* __restrict__ n1p,
                          const float* __restrict__ n2p,
                          float4* __restrict__ out4)
{
    const int t = blockIdx.x * blockDim.x + threadIdx.x;  // grid sized exactly
    const int p = t >> 1;      // pair index: rays 4p..4p+3
    const int s = t & 1;
    const long i3 = 3L * p;

    // Even (s=0): f0 and f1. Odd (s=1): f2.
    float4 Pa, Pb, Va, Vb;
    if (s == 0) {
        Pa = __ldcs(&P4[i3 + 0]);   // f0
        Pb = __ldcs(&P4[i3 + 1]);   // f1
        Va = __ldcs(&V4[i3 + 0]);
        Vb = __ldcs(&V4[i3 + 1]);
    } else {
        Pa = __ldcs(&P4[i3 + 2]);   // f2
        Va = __ldcs(&V4[i3 + 2]);
        Pb = make_float4(0.f, 0.f, 0.f, 0.f);
        Vb = make_float4(0.f, 0.f, 0.f, 0.f);
    }

    // Cross-lane: odd needs even's f1.z, f1.w (for P and V). 4 shfl.b32.
    float p1z = __shfl_xor_sync(0xffffffffu, Pb.z, 1);
    float p1w = __shfl_xor_sync(0xffffffffu, Pb.w, 1);
    float v1z = __shfl_xor_sync(0xffffffffu, Vb.z, 1);
    float v1w = __shfl_xor_sync(0xffffffffu, Vb.w, 1);

    const float R0   = Rp[0];
    const float eta  = n1p[0] / n2p[0];
    const float Cx   = Z0f + R0;
    const float invR = 1.0f / R0;
    const float eta2 = eta * eta;

    // Ray selection:
    // even: rayA = f0.xyz            rayB = (f0.w, f1.x, f1.y)
    // odd : rayA = (f1.z, f1.w, f2.x) rayB = f2.yzw      (f1.zw via shfl)
    float pax, pay, paz, pbx, pby, pbz;
    float vax, vay, vaz, vbx, vby, vbz;
    if (s == 0) {
        pax = Pa.x; pay = Pa.y; paz = Pa.z;
        pbx = Pa.w; pby = Pb.x; pbz = Pb.y;
        vax = Va.x; vay = Va.y; vaz = Va.z;
        vbx = Va.w; vby = Vb.x; vbz = Vb.y;
    } else {
        pax = p1z;  pay = p1w;  paz = Pa.x;
        pbx = Pa.y; pby = Pa.z; pbz = Pa.w;
        vax = v1z;  vay = v1w;  vaz = Va.x;
        vbx = Va.y; vby = Va.z; vbz = Va.w;
    }

    float of[12];
    trace_ray(pax, pay, paz, vax, vay, vaz, R0, Cx, invR, eta, eta2, of);
    trace_ray(pbx, pby, pbz, vbx, vby, vbz, R0, Cx, invR, eta, eta2, of + 6);

    // Store 3 aligned float4: even -> out4[6p+0..2], odd -> out4[6p+3..5]
    const long obase = 6L * p + 3 * s;
    __stcs(&out4[obase + 0], make_float4(of[0], of[1], of[2],  of[3]));
    __stcs(&out4[obase + 1], make_float4(of[4], of[5], of[6],  of[7]));
    __stcs(&out4[obase + 2], make_float4(of[8], of[9], of[10], of[11]));
}

// Scalar tail for leftover rays. Not hit for N = 8388608.
__global__ void refract_tail_kernel(const float* __restrict__ P,
                                    const float* __restrict__ V,
                                    const float* __restrict__ Rp,
                                    const float* __restrict__ n1p,
                                    const float* __restrict__ n2p,
                                    float* __restrict__ out,
                                    int start, int N)
{
    int n = start + blockIdx.x * blockDim.x + threadIdx.x;
    if (n >= N) return;

    const float R0   = Rp[0];
    const float eta  = n1p[0] / n2p[0];
    const float Cx   = Z0f + R0;
    const float invR = 1.0f / R0;

    float px = P[3*n+0], py = P[3*n+1], pz = P[3*n+2];
    float vx = V[3*n+0], vy = V[3*n+1], vz = V[3*n+2];

    float pcx = px - Cx, pcy = py, pcz = pz;
    float b = 2.0f * (vx*pcx + vy*pcy + vz*pcz);
    float c = pcx*pcx + pcy*pcy + pcz*pcz - R0*R0;
    float disc = b*b - 4.0f*c;
    float sd = sqrtf(fmaxf(disc, 0.0f));
    float t1 = (-b - sd) * 0.5f;
    float t2 = (-b + sd) * 0.5f;
    float t  = (t1 > EPSf) ? t1 : t2;
    bool hit = (disc >= 0.0f) && (t > EPSf);

    float qx = px + t*vx, qy = py + t*vy, qz = pz + t*vz;
    float r2 = qy*qy + qz*qz;
    hit = hit && (r2 <= AP_R2);

    float nx = (qx - Cx) * invR, ny = qy * invR, nz = qz * invR;
    float ndotv = nx*vx + ny*vy + nz*vz;
    if (ndotv > 0.0f) { nx = -nx; ny = -ny; nz = -nz; }

    float cosi  = -(nx*vx + ny*vy + nz*vz);
    float sin2t = eta*eta * (1.0f - cosi*cosi);
    bool refract_ok = (sin2t <= 1.0f);
    float cost = sqrtf(fmaxf(1.0f - sin2t, 0.0f));
    float k = eta*cosi - cost;

    bool valid = hit && refract_ok;
    out[6*n+0] = valid ? qx : 0.0f;
    out[6*n+1] = valid ? qy : 0.0f;
    out[6*n+2] = valid ? qz : 0.0f;
    out[6*n+3] = valid ? (eta*vx + k*nx) : 0.0f;
    out[6*n+4] = valid ? (eta*vy + k*ny) : 0.0f;
    out[6*n+5] = valid ? (eta*vz + k*nz) : 0.0f;
}

extern "C" void kernel_launch(void* const* d_in, const int* in_sizes, int n_in,
                              void* d_out, int out_size)
{
    const float* P  = (const float*)d_in[0];
    const float* V  = (const float*)d_in[1];
    const float* R  = (const float*)d_in[2];
    const float* n1 = (const float*)d_in[3];
    const float* n2 = (const float*)d_in[4];
    float* out = (float*)d_out;

    int N = in_sizes[0] / 3;            // rays
    // Full blocks only (512 rays per block) so every warp is complete.
    long nGroups = N / 4;               // thread pairs
    long threadsWanted = nGroups * 2;
    long fullBlocks = threadsWanted / 256;
    long rays_main = fullBlocks * 512;

    if (fullBlocks > 0) {
        refract_shfl2_kernel<<<(unsigned)fullBlocks, 256>>>(
            (const float4*)P, (const float4*)V, R, n1, n2, (float4*)out);
    }
    if (rays_main < N) {
        int rem = (int)(N - rays_main);
        refract_tail_kernel<<<(rem + 255) / 256, 256>>>(
            P, V, R, n1, n2, out, (int)rays_main, N);
    }
}

// round 11
// speedup vs baseline: 1.5250x; 1.0015x over previous
#include <cuda_runtime.h>

#define Z0f 10.0f
#define EPSf 1e-6f
#define AP_R2 400.0f   // (DIAMETER*0.5)^2

// One ray: inputs (px..vz), writes 6 floats into o[0..5].
__device__ __forceinline__ void trace_ray(float px, float py, float pz,
                                          float vx, float vy, float vz,
                                          float R0, float Cx, float invR,
                                          float eta, float eta2,
                                          float* o)
{
    // sphere intersection: t^2 + b t + c = 0  (|V| = 1)
    float pcx = px - Cx, pcy = py, pcz = pz;
    float b = 2.0f * (vx*pcx + vy*pcy + vz*pcz);
    float c = pcx*pcx + pcy*pcy + pcz*pcz - R0*R0;
    float disc = b*b - 4.0f*c;
    float sd = sqrtf(fmaxf(disc, 0.0f));
    float t1 = (-b - sd) * 0.5f;
    float t2 = (-b + sd) * 0.5f;
    float t  = (t1 > EPSf) ? t1 : t2;
    bool hit = (disc >= 0.0f) && (t > EPSf);

    // collision point + aperture clip
    float qx = px + t*vx, qy = py + t*vy, qz = pz + t*vz;
    float r2 = qy*qy + qz*qz;
    hit = hit && (r2 <= AP_R2);

    // surface normal oriented against the ray
    float nx = (qx - Cx) * invR, ny = qy * invR, nz = qz * invR;
    float ndotv = nx*vx + ny*vy + nz*vz;
    if (ndotv > 0.0f) { nx = -nx; ny = -ny; nz = -nz; }

    // Snell refraction (vector form)
    float cosi  = -(nx*vx + ny*vy + nz*vz);
    float sin2t = eta2 * (1.0f - cosi*cosi);
    bool refract_ok = (sin2t <= 1.0f);
    float cost = sqrtf(fmaxf(1.0f - sin2t, 0.0f));
    float k = eta*cosi - cost;

    bool valid = hit && refract_ok;
    o[0] = valid ? qx : 0.0f;
    o[1] = valid ? qy : 0.0f;
    o[2] = valid ? qz : 0.0f;
    o[3] = valid ? (eta*vx + k*nx) : 0.0f;
    o[4] = valid ? (eta*vy + k*ny) : 0.0f;
    o[5] = valid ? (eta*vz + k*nz) : 0.0f;
}

// 2 rays/thread; a thread-pair owns 4 rays = 3 float4 of P/V, 6 float4 out.
// Balanced: even lane loads P0,P1,V0; odd lane loads V1,V2,P2 (3 LDG.128 each).
// Exchange: P1.zw -> odd, V1.xy -> even (4 shfl.b32/thread). No smem/barriers.
__global__ __launch_bounds__(256, 8)
void refract_shfl3_kernel(const float4* __restrict__ P4,
                          const float4* __restrict__ V4,
                          const float* __restrict__ Rp,
                          const float* __restrict__ n1p,
                          const float* __restrict__ n2p,
                          float4* __restrict__ out4)
{
    const int t = blockIdx.x * blockDim.x + threadIdx.x;  // grid sized exactly
    const int p = t >> 1;      // pair index: rays 4p..4p+3
    const int s = t & 1;
    const long i3 = 3L * p;

    // Uniform scalars first (L1-broadcast, off the critical path).
    const float R0   = Rp[0];
    const float eta  = n1p[0] / n2p[0];
    const float Cx   = Z0f + R0;
    const float invR = 1.0f / R0;
    const float eta2 = eta * eta;

    // Balanced loads: 3 LDG.128 per lane.
    // even: A=P0, B=P1, C=V0    odd: A=P2, B=V1, C=V2
    float4 A, B, C;
    if (s == 0) {
        A = __ldcs(&P4[i3 + 0]);
        B = __ldcs(&P4[i3 + 1]);
        C = __ldcs(&V4[i3 + 0]);
    } else {
        A = __ldcs(&P4[i3 + 2]);
        B = __ldcs(&V4[i3 + 1]);
        C = __ldcs(&V4[i3 + 2]);
    }

    // Cross-lane exchange within the pair (4 shfl.b32):
    //   even sends B.z,B.w (= P1.zw) -> odd receives as x0,x1
    //   odd  sends B.x,B.y (= V1.xy) -> even receives as x0,x1
    float sendL = (s == 0) ? B.z : B.x;
    float sendH = (s == 0) ? B.w : B.y;
    float x0 = __shfl_xor_sync(0xffffffffu, sendL, 1);
    float x1 = __shfl_xor_sync(0xffffffffu, sendH, 1);

    // Ray selection:
    // even: rayA P = A.xyz            rayA V = C.xyz
    //       rayB P = (A.w, B.x, B.y)  rayB V = (C.w, x0, x1)   [x=V1.xy]
    // odd : rayA P = (x0, x1, A.x)    rayA V = (B.z, B.w, C.x) [x=P1.zw]
    //       rayB P = A.yzw            rayB V = C.yzw
    float pax, pay, paz, pbx, pby, pbz;
    float vax, vay, vaz, vbx, vby, vbz;
    if (s == 0) {
        pax = A.x; pay = A.y; paz = A.z;
        pbx = A.w; pby = B.x; pbz = B.y;
        vax = C.x; vay = C.y; vaz = C.z;
        vbx = C.w; vby = x0;  vbz = x1;
    } else {
        pax = x0;  pay = x1;  paz = A.x;
        pbx = A.y; pby = A.z; pbz = A.w;
        vax = B.z; vay = B.w; vaz = C.x;
        vbx = C.y; vby = C.z; vbz = C.w;
    }

    float of[12];
    trace_ray(pax, pay, paz, vax, vay, vaz, R0, Cx, invR, eta, eta2, of);
    trace_ray(pbx, pby, pbz, vbx, vby, vbz, R0, Cx, invR, eta, eta2, of + 6);

    // Store 3 aligned float4: even -> out4[6p+0..2], odd -> out4[6p+3..5]
    const long obase = 6L * p + 3 * s;
    __stcs(&out4[obase + 0], make_float4(of[0], of[1], of[2],  of[3]));
    __stcs(&out4[obase + 1], make_float4(of[4], of[5], of[6],  of[7]));
    __stcs(&out4[obase + 2], make_float4(of[8], of[9], of[10], of[11]));
}

// Scalar tail for leftover rays. Not hit for N = 8388608.
__global__ void refract_tail_kernel(const float* __restrict__ P,
                                    const float* __restrict__ V,
                                    const float* __restrict__ Rp,
                                    const float* __restrict__ n1p,
                                    const float* __restrict__ n2p,
                                    float* __restrict__ out,
                                    int start, int N)
{
    int n = start + blockIdx.x * blockDim.x + threadIdx.x;
    if (n >= N) return;

    const float R0   = Rp[0];
    const float eta  = n1p[0] / n2p[0];
    const float Cx   = Z0f + R0;
    const float invR = 1.0f / R0;

    float px = P[3*n+0], py = P[3*n+1], pz = P[3*n+2];
    float vx = V[3*n+0], vy = V[3*n+1], vz = V[3*n+2];

    float pcx = px - Cx, pcy = py, pcz = pz;
    float b = 2.0f * (vx*pcx + vy*pcy + vz*pcz);
    float c = pcx*pcx + pcy*pcy + pcz*pcz - R0*R0;
    float disc = b*b - 4.0f*c;
    float sd = sqrtf(fmaxf(disc, 0.0f));
    float t1 = (-b - sd) * 0.5f;
    float t2 = (-b + sd) * 0.5f;
    float t  = (t1 > EPSf) ? t1 : t2;
    bool hit = (disc >= 0.0f) && (t > EPSf);

    float qx = px + t*vx, qy = py + t*vy, qz = pz + t*vz;
    float r2 = qy*qy + qz*qz;
    hit = hit && (r2 <= AP_R2);

    float nx = (qx - Cx) * invR, ny = qy * invR, nz = qz * invR;
    float ndotv = nx*vx + ny*vy + nz*vz;
    if (ndotv > 0.0f) { nx = -nx; ny = -ny; nz = -nz; }

    float cosi  = -(nx*vx + ny*vy + nz*vz);
    float sin2t = eta*eta * (1.0f - cosi*cosi);
    bool refract_ok = (sin2t <= 1.0f);
    float cost = sqrtf(fmaxf(1.0f - sin2t, 0.0f));
    float k = eta*cosi - cost;

    bool valid = hit && refract_ok;
    out[6*n+0] = valid ? qx : 0.0f;
    out[6*n+1] = valid ? qy : 0.0f;
    out[6*n+2] = valid ? qz : 0.0f;
    out[6*n+3] = valid ? (eta*vx + k*nx) : 0.0f;
    out[6*n+4] = valid ? (eta*vy + k*ny) : 0.0f;
    out[6*n+5] = valid ? (eta*vz + k*nz) : 0.0f;
}

extern "C" void kernel_launch(void* const* d_in, const int* in_sizes, int n_in,
                              void* d_out, int out_size)
{
    const float* P  = (const float*)d_in[0];
    const float* V  = (const float*)d_in[1];
    const float* R  = (const float*)d_in[2];
    const float* n1 = (const float*)d_in[3];
    const float* n2 = (const float*)d_in[4];
    float* out = (float*)d_out;

    int N = in_sizes[0] / 3;            // rays
    // Full blocks only (512 rays per block) so every warp is complete.
    long nGroups = N / 4;               // thread pairs
    long threadsWanted = nGroups * 2;
    long fullBlocks = threadsWanted / 256;
    long rays_main = fullBlocks * 512;

    if (fullBlocks > 0) {
        refract_shfl3_kernel<<<(unsigned)fullBlocks, 256>>>(
            (const float4*)P, (const float4*)V, R, n1, n2, (float4*)out);
    }
    if (rays_main < N) {
        int rem = (int)(N - rays_main);
        refract_tail_kernel<<<(rem + 255) / 256, 256>>>(
            P, V, R, n1, n2, out, (int)rays_main, N);
    }
}